// round 15
// baseline (speedup 1.0000x reference)
#include <cuda_runtime.h>
#include <cuda_fp16.h>
#include <cstdint>

// Problem shape (fixed)
#define Bb    4
#define T     1024
#define E     512
#define H     8
#define MTOT  (Bb*T)       // 4096
#define NPROJ (H*E)        // 4096
#define BH    (Bb*H)       // 32

#define NEG_INF (__int_as_float(0xff800000))
#define QK_SCALE 0.21022410381342864f   // 512^-0.25

typedef __half f16;

// ---------------- scratch (device globals; no allocs allowed) ----------------
__device__ __align__(16) f16 g_x[MTOT * E];
__device__ __align__(16) f16 g_wk[NPROJ * E];
__device__ __align__(16) f16 g_wq[NPROJ * E];
__device__ __align__(16) f16 g_wv[NPROJ * E];
__device__ __align__(16) f16 g_wu[E * NPROJ];
__device__ __align__(16) f16 g_q[MTOT * NPROJ];        // pre-scaled
__device__ __align__(16) f16 g_k[MTOT * NPROJ];        // pre-scaled
__device__ __align__(16) f16 g_vt[(size_t)BH * E * T]; // (b,h,e,t)
__device__ __align__(16) f16 g_s[(size_t)BH * T * T];  // fp16 scores
__device__ __align__(16) f16 g_p[(size_t)BH * T * T];
__device__ __align__(16) f16 g_ao[MTOT * NPROJ];

// ---------------------------------------------------------------------------
__device__ __forceinline__ uint32_t smem_u32(const void* p) {
    uint32_t a;
    asm("{ .reg .u64 t; cvta.to.shared.u64 t, %1; cvt.u32.u64 %0, t; }" : "=r"(a) : "l"(p));
    return a;
}
__device__ __forceinline__ void cp16(uint32_t dst, const void* src) {
    asm volatile("cp.async.cg.shared.global [%0], [%1], 16;" :: "r"(dst), "l"(src) : "memory");
}
#define CP_COMMIT()  asm volatile("cp.async.commit_group;" ::: "memory")
#define CP_WAIT(n)   asm volatile("cp.async.wait_group %0;" :: "n"(n) : "memory")

__device__ __forceinline__ void ldsm4(uint32_t* r, uint32_t addr) {
    asm volatile("ldmatrix.sync.aligned.m8n8.x4.shared.b16 {%0,%1,%2,%3}, [%4];"
                 : "=r"(r[0]), "=r"(r[1]), "=r"(r[2]), "=r"(r[3]) : "r"(addr));
}
__device__ __forceinline__ void mma16816(float* c, const uint32_t* a, const uint32_t* b) {
    asm volatile(
        "mma.sync.aligned.m16n8k16.row.col.f32.f16.f16.f32 "
        "{%0,%1,%2,%3}, {%4,%5,%6,%7}, {%8,%9}, {%0,%1,%2,%3};"
        : "+f"(c[0]), "+f"(c[1]), "+f"(c[2]), "+f"(c[3])
        : "r"(a[0]), "r"(a[1]), "r"(a[2]), "r"(a[3]), "r"(b[0]), "r"(b[1]));
}

// all 5 inputs -> single fp16; each is 2M elements, float4-vectorized
__global__ void split_all(const float* __restrict__ x,  const float* __restrict__ wk,
                          const float* __restrict__ wq, const float* __restrict__ wv,
                          const float* __restrict__ wu) {
    const int i4 = blockIdx.x * 256 + threadIdx.x;    // float4 index
    const float* s; f16* d;
    switch (blockIdx.y) {
        case 0:  s = x;  d = g_x;  break;
        case 1:  s = wk; d = g_wk; break;
        case 2:  s = wq; d = g_wq; break;
        case 3:  s = wv; d = g_wv; break;
        default: s = wu; d = g_wu; break;
    }
    float4 v = ((const float4*)s)[i4];
    f16 o[4] = { __float2half(v.x), __float2half(v.y),
                 __float2half(v.z), __float2half(v.w) };
    *(uint2*)(d + i4 * 4) = *(const uint2*)o;
}

// swizzle for ROWB-byte rows; kg = 16B group.  XOR with (row & 7) keeps
// ldmatrix (8 rows, same kg) conflict-free.
template<int ROWB>
__device__ __forceinline__ uint32_t swz(int row, int kg) {
    return row * ROWB + ((kg ^ (row & 7)) << 4);
}

// ---------------------------------------------------------------------------
// GEMM core (1-mma): C[BM,BN] = A[BM,K] x B[BN,K]^T, both single fp16.
// 256 threads, warp grid 4(m) x 2(n), warp tile BM/4 x BN/2, K-chunk CK,
// 3-stage cp.async (one chunk always in flight), ONE __syncthreads per chunk.
// ---------------------------------------------------------------------------
template<int BM, int BN, int CK>
__device__ __forceinline__ void tc_gemm1(
    const f16* __restrict__ A, int lda,
    const f16* __restrict__ B, int ldb,
    int K, float* acc)
{
    constexpr int WM = BM / 4, WN = BN / 2;
    constexpr int ROWB = CK * 2;
    constexpr int KG = CK / 8;            // 16B groups per row
    constexpr int SA = BM * ROWB;
    constexpr int SB = BN * ROWB;
    constexpr int STG = SA + SB;
    extern __shared__ char sm[];

    const int tid  = threadIdx.x;
    const int lane = tid & 31;
    const int warp = tid >> 5;
    const int wm = warp >> 1, wn = warp & 1;

    const int arow = ((lane >> 3) & 1) * 8 + (lane & 7);
    const int akg  = (lane >> 4) & 1;
    const int brow = ((lane >> 4) & 1) * 8 + (lane & 7);
    const int bkg  = (lane >> 3) & 1;

    #pragma unroll
    for (int i = 0; i < WM * WN / 32; i++) acc[i] = 0.f;

    const int nch = K / CK;

    auto load_chunk = [&](int i) {
        const int k0 = i * CK;
        const uint32_t st = smem_u32(sm + (i % 3) * STG);
        #pragma unroll
        for (int j = 0; j < BM * CK / 2048; j++) {     // 4 KB per 256-thread pass
            int idx = tid + j * 256;
            int r = idx / KG, kg = idx % KG;
            cp16(st + swz<ROWB>(r, kg), A + (size_t)r * lda + k0 + kg * 8);
        }
        #pragma unroll
        for (int j = 0; j < BN * CK / 2048; j++) {
            int idx = tid + j * 256;
            int r = idx / KG, kg = idx % KG;
            cp16(st + SA + swz<ROWB>(r, kg), B + (size_t)r * ldb + k0 + kg * 8);
        }
        CP_COMMIT();
    };

    load_chunk(0);
    if (nch > 1) load_chunk(1);

    for (int i = 0; i < nch; i++) {
        if (i + 1 < nch) { CP_WAIT(1); } else { CP_WAIT(0); }
        __syncthreads();
        if (i + 2 < nch) load_chunk(i + 2);   // buffer (i+2)%3 last read iter i-1

        const uint32_t st = smem_u32(sm + (i % 3) * STG);
        #pragma unroll
        for (int ks = 0; ks < CK / 16; ks++) {
            uint32_t a[WM / 16][4], b[WN / 16][4];
            #pragma unroll
            for (int im = 0; im < WM / 16; im++) {
                int row = wm * WM + im * 16 + arow;
                ldsm4(a[im], st + swz<ROWB>(row, ks * 2 + akg));
            }
            #pragma unroll
            for (int j2 = 0; j2 < WN / 16; j2++) {
                int n = wn * WN + j2 * 16 + brow;
                ldsm4(b[j2], st + SA + swz<ROWB>(n, ks * 2 + bkg));
            }
            #pragma unroll
            for (int im = 0; im < WM / 16; im++)
                #pragma unroll
                for (int jn = 0; jn < WN / 8; jn++)
                    mma16816(acc + (im * (WN / 8) + jn) * 4,
                             a[im], &b[jn >> 1][(jn & 1) * 2]);
        }
    }
}

// packed epilogue: f(row, col, v0, v1) for adjacent column pairs (col, col+1)
template<int BM, int BN, typename F>
__device__ __forceinline__ void epi2(const float* acc, F&& f) {
    constexpr int WM = BM / 4, WN = BN / 2;
    const int lane = threadIdx.x & 31;
    const int warp = threadIdx.x >> 5;
    const int wm = warp >> 1, wn = warp & 1;
    const int g = lane >> 2, tg = lane & 3;
    #pragma unroll
    for (int im = 0; im < WM / 16; im++)
        #pragma unroll
        for (int jn = 0; jn < WN / 8; jn++)
            #pragma unroll
            for (int rp = 0; rp < 2; rp++) {
                int row = wm * WM + im * 16 + g + rp * 8;
                int col = wn * WN + jn * 8 + tg * 2;
                const float* c = acc + (im * (WN / 8) + jn) * 4 + rp * 2;
                f(row, col, c[0], c[1]);
            }
}

__device__ __forceinline__ void st_h2(f16* p, float v0, float v1) {
    *(__half2*)p = __halves2half2(__float2half(v0), __float2half(v1));
}

// CK=64 BN=128 kernels: stage (128+128)*128 = 32 KB, x3 = 96 KB
#define SMEM_G128  (3 * (128 + 128) * 128)
// proj also stages a 128x129 fp32 tile (66 KB) — fits inside 96 KB
#define SMEM_PROJ  SMEM_G128
// unify: BN=64, CK=64: stage (128+64)*128 = 24 KB, x3 = 72 KB
#define SMEM_UNIFY (3 * (128 + 64) * 128)

// ---------------------------------------------------------------------------
// QKV projection (BM=128, BN=128, CK=64).
// z: 0 = k (scaled), 1 = q (scaled), 2 = v -> Vt (staged via smem, coalesced)
// ---------------------------------------------------------------------------
__global__ __launch_bounds__(256, 2) void proj_kernel() {
    const int n0 = blockIdx.x * 128;
    const int m0 = blockIdx.y * 128;
    const int z  = blockIdx.z;
    const f16* W = (z == 0) ? g_wk : (z == 1) ? g_wq : g_wv;

    float acc[64];
    tc_gemm1<128, 128, 64>(g_x + (size_t)m0 * E, E, W + (size_t)n0 * E, E, E, acc);

    if (z == 2) {
        extern __shared__ char sm[];
        float* smf = (float*)sm;              // 128 x 129 fp32 = 66 KB
        __syncthreads();
        epi2<128, 128>(acc, [&](int row, int col, float v0, float v1) {
            smf[row * 129 + col]     = v0;
            smf[row * 129 + col + 1] = v1;
        });
        __syncthreads();
        const int b = m0 >> 10, t_base = m0 & 1023;
        const int h = n0 >> 9,  ec_base = n0 & 511;
        const size_t vb = ((size_t)((b * H + h) * E + ec_base)) * T + t_base;
        const int tid = threadIdx.x;
        #pragma unroll
        for (int j = 0; j < 32; j++) {
            int idx = tid + j * 256;          // 8192 (ec, t-pair) units
            int ec_i = idx >> 6, t_i = (idx & 63) * 2;
            st_h2(g_vt + vb + (size_t)ec_i * T + t_i,
                  smf[t_i * 129 + ec_i], smf[(t_i + 1) * 129 + ec_i]);
        }
    } else {
        f16* D = (z == 0) ? g_k : g_q;
        epi2<128, 128>(acc, [&](int row, int col, float v0, float v1) {
            st_h2(D + (size_t)(m0 + row) * NPROJ + n0 + col,
                  v0 * QK_SCALE, v1 * QK_SCALE);
        });
    }
}

// ---------------------------------------------------------------------------
// Scores (BM=128 q, BN=128 k, CK=64): lower-triangle tiles only, q reversed.
// S stored fp16, half2-packed.
// ---------------------------------------------------------------------------
__global__ __launch_bounds__(256, 2) void scores_kernel() {
    const int k0 = blockIdx.x * 128;
    const int q0 = (int)(gridDim.y - 1 - blockIdx.y) * 128;
    if (k0 > q0) return;
    const int bh = blockIdx.z;
    const int b = bh >> 3, h = bh & 7;
    const size_t base = (size_t)b * T * NPROJ + (size_t)h * E;

    float acc[64];
    tc_gemm1<128, 128, 64>(g_q + base + (size_t)q0 * NPROJ, NPROJ,
                           g_k + base + (size_t)k0 * NPROJ, NPROJ, E, acc);

    f16* S = g_s + (size_t)bh * T * T;
    epi2<128, 128>(acc, [&](int row, int col, float v0, float v1) {
        st_h2(S + (size_t)(q0 + row) * T + k0 + col, v0, v1);
    });
}

// ---------------------------------------------------------------------------
// Softmax: fp16 score loads, shuffle reductions, single fp16 prob output.
// Writes only k < roundup128(trow+1).
// ---------------------------------------------------------------------------
__global__ void softmax_kernel() {
    const int row = blockIdx.x;
    const int trow = row & 1023;
    const int kend = (trow & ~127) + 128;
    const f16* __restrict__ S = g_s + (size_t)row * T;
    f16* __restrict__ P = g_p + (size_t)row * T;
    const int tid = threadIdx.x;
    const int lane = tid & 31, warp = tid >> 5;
    __shared__ float red[8];

    const int base = tid * 4;
    f16 s4[4];
    *(uint2*)s4 = *(const uint2*)(S + base);
    float v[4];
    #pragma unroll
    for (int i = 0; i < 4; i++)
        v[i] = (base + i <= trow) ? __half2float(s4[i]) : NEG_INF;

    float m = fmaxf(fmaxf(v[0], v[1]), fmaxf(v[2], v[3]));
    #pragma unroll
    for (int o = 16; o > 0; o >>= 1) m = fmaxf(m, __shfl_xor_sync(~0u, m, o));
    if (lane == 0) red[warp] = m;
    __syncthreads();
    m = red[0];
    #pragma unroll
    for (int w = 1; w < 8; w++) m = fmaxf(m, red[w]);
    __syncthreads();

    float sum = 0.f;
    #pragma unroll
    for (int i = 0; i < 4; i++) { v[i] = __expf(v[i] - m); sum += v[i]; }
    #pragma unroll
    for (int o = 16; o > 0; o >>= 1) sum += __shfl_xor_sync(~0u, sum, o);
    if (lane == 0) red[warp] = sum;
    __syncthreads();
    sum = red[0];
    #pragma unroll
    for (int w = 1; w < 8; w++) sum += red[w];

    const float inv = 1.0f / sum;
    if (base < kend) {
        f16 p[4];
        #pragma unroll
        for (int i = 0; i < 4; i++) p[i] = __float2half(v[i] * inv);
        *(uint2*)(P + base) = *(const uint2*)p;
    }
}

// ---------------------------------------------------------------------------
// AV (BM=128 q, BN=128 e, CK=64): K truncated causally; q reversed.
// ---------------------------------------------------------------------------
__global__ __launch_bounds__(256, 2) void av_kernel() {
    const int n0 = blockIdx.x * 128;
    const int q0 = (int)(gridDim.y - 1 - blockIdx.y) * 128;
    const int bh = blockIdx.z;
    const int b = bh >> 3, h = bh & 7;
    const size_t pbase = (size_t)bh * T * T + (size_t)q0 * T;
    const size_t vbase = (size_t)bh * E * T + (size_t)n0 * T;

    float acc[64];
    tc_gemm1<128, 128, 64>(g_p + pbase, T, g_vt + vbase, T, q0 + 128, acc);

    epi2<128, 128>(acc, [&](int row, int col, float v0, float v1) {
        size_t o = (size_t)(b * T + q0 + row) * NPROJ + h * E + n0 + col;
        st_h2(g_ao + o, v0, v1);
    });
}

// ---------------------------------------------------------------------------
// Unify (BM=128, BN=64, CK=64): grid 8x32 keeps the chip filled.
// out = AO @ wu^T + bu  (float2-packed stores)
// ---------------------------------------------------------------------------
__global__ __launch_bounds__(256, 2) void unify_kernel(const float* __restrict__ bu,
                                                       float* __restrict__ out) {
    const int n0 = blockIdx.x * 64;
    const int m0 = blockIdx.y * 128;

    float acc[32];
    tc_gemm1<128, 64, 64>(g_ao + (size_t)m0 * NPROJ, NPROJ,
                          g_wu + (size_t)n0 * NPROJ, NPROJ, NPROJ, acc);

    epi2<128, 64>(acc, [&](int row, int col, float v0, float v1) {
        int n = n0 + col;
        float2 o = make_float2(v0 + bu[n], v1 + bu[n + 1]);
        *(float2*)(out + (size_t)(m0 + row) * E + n) = o;
    });
}

// ---------------------------------------------------------------------------
extern "C" void kernel_launch(void* const* d_in, const int* in_sizes, int n_in,
                              void* d_out, int out_size) {
    const float* x  = (const float*)d_in[0];
    const float* wk = (const float*)d_in[1];
    const float* wq = (const float*)d_in[2];
    const float* wv = (const float*)d_in[3];
    const float* wu = (const float*)d_in[4];
    const float* bu = (const float*)d_in[5];
    float* out = (float*)d_out;

    cudaFuncSetAttribute(proj_kernel,   cudaFuncAttributeMaxDynamicSharedMemorySize, SMEM_PROJ);
    cudaFuncSetAttribute(scores_kernel, cudaFuncAttributeMaxDynamicSharedMemorySize, SMEM_G128);
    cudaFuncSetAttribute(av_kernel,     cudaFuncAttributeMaxDynamicSharedMemorySize, SMEM_G128);
    cudaFuncSetAttribute(unify_kernel,  cudaFuncAttributeMaxDynamicSharedMemorySize, SMEM_UNIFY);

    split_all<<<dim3(MTOT * E / 1024, 5), 256>>>(x, wk, wq, wv, wu);

    proj_kernel  <<<dim3(NPROJ / 128, MTOT / 128, 3), 256, SMEM_PROJ>>>();
    scores_kernel<<<dim3(T / 128, T / 128, BH),        256, SMEM_G128>>>();
    softmax_kernel<<<BH * T, 256>>>();
    av_kernel    <<<dim3(E / 128, T / 128, BH),        256, SMEM_G128>>>();
    unify_kernel <<<dim3(E / 64, MTOT / 128),          256, SMEM_UNIFY>>>(bu, out);
}

// round 16
// speedup vs baseline: 1.0162x; 1.0162x over previous
#include <cuda_runtime.h>
#include <cuda_fp16.h>
#include <cstdint>

// Problem shape (fixed)
#define Bb    4
#define T     1024
#define E     512
#define H     8
#define MTOT  (Bb*T)       // 4096
#define NPROJ (H*E)        // 4096
#define BH    (Bb*H)       // 32

#define NEG_INF (__int_as_float(0xff800000))
#define QK_SCALE 0.21022410381342864f   // 512^-0.25

typedef __half f16;

// ---------------- scratch (device globals; no allocs allowed) ----------------
__device__ __align__(16) f16 g_x[MTOT * E];
__device__ __align__(16) f16 g_wk[NPROJ * E];
__device__ __align__(16) f16 g_wq[NPROJ * E];
__device__ __align__(16) f16 g_wv[NPROJ * E];
__device__ __align__(16) f16 g_wu[E * NPROJ];
__device__ __align__(16) f16 g_q[MTOT * NPROJ];        // pre-scaled
__device__ __align__(16) f16 g_k[MTOT * NPROJ];        // pre-scaled
__device__ __align__(16) f16 g_vt[(size_t)BH * E * T]; // (b,h,e,t)
__device__ __align__(16) f16 g_s[(size_t)BH * T * T];  // fp16 scores
__device__ __align__(16) f16 g_p[(size_t)BH * T * T];
__device__ __align__(16) f16 g_ao[MTOT * NPROJ];

// ---------------------------------------------------------------------------
__device__ __forceinline__ uint32_t smem_u32(const void* p) {
    uint32_t a;
    asm("{ .reg .u64 t; cvta.to.shared.u64 t, %1; cvt.u32.u64 %0, t; }" : "=r"(a) : "l"(p));
    return a;
}
__device__ __forceinline__ void cp16(uint32_t dst, const void* src) {
    asm volatile("cp.async.cg.shared.global [%0], [%1], 16;" :: "r"(dst), "l"(src) : "memory");
}
#define CP_COMMIT()  asm volatile("cp.async.commit_group;" ::: "memory")
#define CP_WAIT(n)   asm volatile("cp.async.wait_group %0;" :: "n"(n) : "memory")

__device__ __forceinline__ void ldsm4(uint32_t* r, uint32_t addr) {
    asm volatile("ldmatrix.sync.aligned.m8n8.x4.shared.b16 {%0,%1,%2,%3}, [%4];"
                 : "=r"(r[0]), "=r"(r[1]), "=r"(r[2]), "=r"(r[3]) : "r"(addr));
}
__device__ __forceinline__ void mma16816(float* c, const uint32_t* a, const uint32_t* b) {
    asm volatile(
        "mma.sync.aligned.m16n8k16.row.col.f32.f16.f16.f32 "
        "{%0,%1,%2,%3}, {%4,%5,%6,%7}, {%8,%9}, {%0,%1,%2,%3};"
        : "+f"(c[0]), "+f"(c[1]), "+f"(c[2]), "+f"(c[3])
        : "r"(a[0]), "r"(a[1]), "r"(a[2]), "r"(a[3]), "r"(b[0]), "r"(b[1]));
}

// all 5 inputs -> single fp16; each is 2M elements, float4-vectorized
__global__ void split_all(const float* __restrict__ x,  const float* __restrict__ wk,
                          const float* __restrict__ wq, const float* __restrict__ wv,
                          const float* __restrict__ wu) {
    const int i4 = blockIdx.x * 256 + threadIdx.x;    // float4 index
    const float* s; f16* d;
    switch (blockIdx.y) {
        case 0:  s = x;  d = g_x;  break;
        case 1:  s = wk; d = g_wk; break;
        case 2:  s = wq; d = g_wq; break;
        case 3:  s = wv; d = g_wv; break;
        default: s = wu; d = g_wu; break;
    }
    float4 v = ((const float4*)s)[i4];
    f16 o[4] = { __float2half(v.x), __float2half(v.y),
                 __float2half(v.z), __float2half(v.w) };
    *(uint2*)(d + i4 * 4) = *(const uint2*)o;
}

// swizzle for ROWB-byte rows; kg = 16B group.  XOR with (row & 7) keeps
// ldmatrix (8 rows, same kg) conflict-free.
template<int ROWB>
__device__ __forceinline__ uint32_t swz(int row, int kg) {
    return row * ROWB + ((kg ^ (row & 7)) << 4);
}

// ---------------------------------------------------------------------------
// GEMM core (1-mma): C[BM,BN] = A[BM,K] x B[BN,K]^T, both single fp16.
// 256 threads, warp grid 4(m) x 2(n), warp tile BM/4 x BN/2, K-chunk CK,
// 2-stage cp.async, ONE __syncthreads per chunk.
// ---------------------------------------------------------------------------
template<int BM, int BN, int CK>
__device__ __forceinline__ void tc_gemm1(
    const f16* __restrict__ A, int lda,
    const f16* __restrict__ B, int ldb,
    int K, float* acc)
{
    constexpr int WM = BM / 4, WN = BN / 2;
    constexpr int ROWB = CK * 2;
    constexpr int KG = CK / 8;            // 16B groups per row
    constexpr int SA = BM * ROWB;
    constexpr int SB = BN * ROWB;
    constexpr int STG = SA + SB;
    extern __shared__ char sm[];

    const int tid  = threadIdx.x;
    const int lane = tid & 31;
    const int warp = tid >> 5;
    const int wm = warp >> 1, wn = warp & 1;

    const int arow = ((lane >> 3) & 1) * 8 + (lane & 7);
    const int akg  = (lane >> 4) & 1;
    const int brow = ((lane >> 4) & 1) * 8 + (lane & 7);
    const int bkg  = (lane >> 3) & 1;

    #pragma unroll
    for (int i = 0; i < WM * WN / 32; i++) acc[i] = 0.f;

    const int nch = K / CK;

    auto load_chunk = [&](int i) {
        const int k0 = i * CK;
        const uint32_t st = smem_u32(sm + (i & 1) * STG);
        #pragma unroll
        for (int j = 0; j < BM * CK / 2048; j++) {     // 4 KB per 256-thread pass
            int idx = tid + j * 256;
            int r = idx / KG, kg = idx % KG;
            cp16(st + swz<ROWB>(r, kg), A + (size_t)r * lda + k0 + kg * 8);
        }
        #pragma unroll
        for (int j = 0; j < BN * CK / 2048; j++) {
            int idx = tid + j * 256;
            int r = idx / KG, kg = idx % KG;
            cp16(st + SA + swz<ROWB>(r, kg), B + (size_t)r * ldb + k0 + kg * 8);
        }
        CP_COMMIT();
    };

    load_chunk(0);

    for (int i = 0; i < nch; i++) {
        CP_WAIT(0);
        __syncthreads();
        if (i + 1 < nch) load_chunk(i + 1);

        const uint32_t st = smem_u32(sm + (i & 1) * STG);
        #pragma unroll
        for (int ks = 0; ks < CK / 16; ks++) {
            uint32_t a[WM / 16][4], b[WN / 16][4];
            #pragma unroll
            for (int im = 0; im < WM / 16; im++) {
                int row = wm * WM + im * 16 + arow;
                ldsm4(a[im], st + swz<ROWB>(row, ks * 2 + akg));
            }
            #pragma unroll
            for (int j2 = 0; j2 < WN / 16; j2++) {
                int n = wn * WN + j2 * 16 + brow;
                ldsm4(b[j2], st + SA + swz<ROWB>(n, ks * 2 + bkg));
            }
            #pragma unroll
            for (int im = 0; im < WM / 16; im++)
                #pragma unroll
                for (int jn = 0; jn < WN / 8; jn++)
                    mma16816(acc + (im * (WN / 8) + jn) * 4,
                             a[im], &b[jn >> 1][(jn & 1) * 2]);
        }
    }
}

// epilogue iteration: f(row, col, val) over this thread's fragment elements
template<int BM, int BN, typename F>
__device__ __forceinline__ void epi(const float* acc, F&& f) {
    constexpr int WM = BM / 4, WN = BN / 2;
    const int lane = threadIdx.x & 31;
    const int warp = threadIdx.x >> 5;
    const int wm = warp >> 1, wn = warp & 1;
    const int g = lane >> 2, tg = lane & 3;
    #pragma unroll
    for (int im = 0; im < WM / 16; im++)
        #pragma unroll
        for (int jn = 0; jn < WN / 8; jn++)
            #pragma unroll
            for (int r = 0; r < 4; r++) {
                int row = wm * WM + im * 16 + g + ((r & 2) ? 8 : 0);
                int col = wn * WN + jn * 8 + tg * 2 + (r & 1);
                f(row, col, acc[(im * (WN / 8) + jn) * 4 + r]);
            }
}

// BN=128/CK=64 kernels: stage (128+128)*128 = 32 KB, x2 = 64 KB
#define SMEM_G128  (2 * (128 + 128) * 128)
// proj additionally stages a 128x129 fp32 tile for the Vt transpose
#define SMEM_PROJ  (128 * 129 * 4 > SMEM_G128 ? 128 * 129 * 4 : SMEM_G128)
// unify: BN=64/CK=128, stage (128+64)*256 = 48 KB, x2 = 96 KB
#define SMEM_UNIFY (2 * (128 + 64) * 256)

// ---------------------------------------------------------------------------
// QKV projection (BM=128, BN=128, CK=64).
// z: 0 = k (scaled), 1 = q (scaled), 2 = v -> Vt (staged via smem, coalesced)
// ---------------------------------------------------------------------------
__global__ __launch_bounds__(256, 2) void proj_kernel() {
    const int n0 = blockIdx.x * 128;
    const int m0 = blockIdx.y * 128;
    const int z  = blockIdx.z;
    const f16* W = (z == 0) ? g_wk : (z == 1) ? g_wq : g_wv;

    float acc[64];
    tc_gemm1<128, 128, 64>(g_x + (size_t)m0 * E, E, W + (size_t)n0 * E, E, E, acc);

    if (z == 2) {
        extern __shared__ char sm[];
        float* smf = (float*)sm;              // 128 x 129 fp32 = 66 KB
        __syncthreads();
        epi<128, 128>(acc, [&](int row, int col, float v) {
            smf[row * 129 + col] = v;
        });
        __syncthreads();
        const int b = m0 >> 10, t_base = m0 & 1023;
        const int h = n0 >> 9,  ec_base = n0 & 511;
        const size_t vb = ((size_t)((b * H + h) * E + ec_base)) * T + t_base;
        const int tid = threadIdx.x;
        #pragma unroll
        for (int j = 0; j < 64; j++) {
            int idx = tid + j * 256;          // 16384 elements
            int ec_i = idx >> 7, t_i = idx & 127;
            g_vt[vb + (size_t)ec_i * T + t_i] = __float2half(smf[t_i * 129 + ec_i]);
        }
    } else {
        f16* D = (z == 0) ? g_k : g_q;
        epi<128, 128>(acc, [&](int row, int col, float v) {
            D[(size_t)(m0 + row) * NPROJ + n0 + col] = __float2half(v * QK_SCALE);
        });
    }
}

// ---------------------------------------------------------------------------
// Scores (BM=128 q, BN=128 k, CK=64): exact triangular grid — 36 active tiles
// per bh, decoded LJF (largest q first).  S stored fp16.
// ---------------------------------------------------------------------------
__global__ __launch_bounds__(256, 2) void scores_kernel() {
    // decode blockIdx.x in [0, 36) -> (qt descending from 7, kt in [0, qt])
    int l = blockIdx.x;
    int qt = 7, cnt = 8;
    while (l >= cnt) { l -= cnt; qt--; cnt = qt + 1; }
    const int q0 = qt * 128;
    const int k0 = l * 128;
    const int bh = blockIdx.z;
    const int b = bh >> 3, h = bh & 7;
    const size_t base = (size_t)b * T * NPROJ + (size_t)h * E;

    float acc[64];
    tc_gemm1<128, 128, 64>(g_q + base + (size_t)q0 * NPROJ, NPROJ,
                           g_k + base + (size_t)k0 * NPROJ, NPROJ, E, acc);

    f16* S = g_s + (size_t)bh * T * T;
    epi<128, 128>(acc, [&](int row, int col, float v) {
        S[(size_t)(q0 + row) * T + k0 + col] = __float2half(v);
    });
}

// ---------------------------------------------------------------------------
// Softmax: fp16 score loads restricted to the valid region (k < kend),
// shuffle reductions, single fp16 prob output.
// ---------------------------------------------------------------------------
__global__ void softmax_kernel() {
    const int row = blockIdx.x;
    const int trow = row & 1023;
    const int kend = (trow & ~127) + 128;
    const f16* __restrict__ S = g_s + (size_t)row * T;
    f16* __restrict__ P = g_p + (size_t)row * T;
    const int tid = threadIdx.x;
    const int lane = tid & 31, warp = tid >> 5;
    __shared__ float red[8];

    const int base = tid * 4;
    float v[4];
    if (base < kend) {
        f16 s4[4];
        *(uint2*)s4 = *(const uint2*)(S + base);
        #pragma unroll
        for (int i = 0; i < 4; i++)
            v[i] = (base + i <= trow) ? __half2float(s4[i]) : NEG_INF;
    } else {
        #pragma unroll
        for (int i = 0; i < 4; i++) v[i] = NEG_INF;
    }

    float m = fmaxf(fmaxf(v[0], v[1]), fmaxf(v[2], v[3]));
    #pragma unroll
    for (int o = 16; o > 0; o >>= 1) m = fmaxf(m, __shfl_xor_sync(~0u, m, o));
    if (lane == 0) red[warp] = m;
    __syncthreads();
    m = red[0];
    #pragma unroll
    for (int w = 1; w < 8; w++) m = fmaxf(m, red[w]);
    __syncthreads();

    float sum = 0.f;
    #pragma unroll
    for (int i = 0; i < 4; i++) { v[i] = __expf(v[i] - m); sum += v[i]; }
    #pragma unroll
    for (int o = 16; o > 0; o >>= 1) sum += __shfl_xor_sync(~0u, sum, o);
    if (lane == 0) red[warp] = sum;
    __syncthreads();
    sum = red[0];
    #pragma unroll
    for (int w = 1; w < 8; w++) sum += red[w];

    const float inv = 1.0f / sum;
    if (base < kend) {
        f16 p[4];
        #pragma unroll
        for (int i = 0; i < 4; i++) p[i] = __float2half(v[i] * inv);
        *(uint2*)(P + base) = *(const uint2*)p;
    }
}

// ---------------------------------------------------------------------------
// AV (BM=128 q, BN=128 e, CK=64): K truncated causally; q reversed (LJF).
// ---------------------------------------------------------------------------
__global__ __launch_bounds__(256, 2) void av_kernel() {
    const int n0 = blockIdx.x * 128;
    const int q0 = (int)(gridDim.y - 1 - blockIdx.y) * 128;
    const int bh = blockIdx.z;
    const int b = bh >> 3, h = bh & 7;
    const size_t pbase = (size_t)bh * T * T + (size_t)q0 * T;
    const size_t vbase = (size_t)bh * E * T + (size_t)n0 * T;

    float acc[64];
    tc_gemm1<128, 128, 64>(g_p + pbase, T, g_vt + vbase, T, q0 + 128, acc);

    epi<128, 128>(acc, [&](int row, int col, float v) {
        size_t o = (size_t)(b * T + q0 + row) * NPROJ + h * E + n0 + col;
        g_ao[o] = __float2half(v);
    });
}

// ---------------------------------------------------------------------------
// Unify (BM=128, BN=64, CK=128): grid 8x32 keeps the chip filled.
// out = AO @ wu^T + bu
// ---------------------------------------------------------------------------
__global__ __launch_bounds__(256, 2) void unify_kernel(const float* __restrict__ bu,
                                                       float* __restrict__ out) {
    const int n0 = blockIdx.x * 64;
    const int m0 = blockIdx.y * 128;

    float acc[32];
    tc_gemm1<128, 64, 128>(g_ao + (size_t)m0 * NPROJ, NPROJ,
                           g_wu + (size_t)n0 * NPROJ, NPROJ, NPROJ, acc);

    epi<128, 64>(acc, [&](int row, int col, float v) {
        out[(size_t)(m0 + row) * E + n0 + col] = v + bu[n0 + col];
    });
}

// ---------------------------------------------------------------------------
extern "C" void kernel_launch(void* const* d_in, const int* in_sizes, int n_in,
                              void* d_out, int out_size) {
    const float* x  = (const float*)d_in[0];
    const float* wk = (const float*)d_in[1];
    const float* wq = (const float*)d_in[2];
    const float* wv = (const float*)d_in[3];
    const float* wu = (const float*)d_in[4];
    const float* bu = (const float*)d_in[5];
    float* out = (float*)d_out;

    cudaFuncSetAttribute(proj_kernel,   cudaFuncAttributeMaxDynamicSharedMemorySize, SMEM_PROJ);
    cudaFuncSetAttribute(scores_kernel, cudaFuncAttributeMaxDynamicSharedMemorySize, SMEM_G128);
    cudaFuncSetAttribute(av_kernel,     cudaFuncAttributeMaxDynamicSharedMemorySize, SMEM_G128);
    cudaFuncSetAttribute(unify_kernel,  cudaFuncAttributeMaxDynamicSharedMemorySize, SMEM_UNIFY);

    split_all<<<dim3(MTOT * E / 1024, 5), 256>>>(x, wk, wq, wv, wu);

    proj_kernel  <<<dim3(NPROJ / 128, MTOT / 128, 3), 256, SMEM_PROJ>>>();
    scores_kernel<<<dim3(36, 1, BH),                   256, SMEM_G128>>>();
    softmax_kernel<<<BH * T, 256>>>();
    av_kernel    <<<dim3(E / 128, T / 128, BH),        256, SMEM_G128>>>();
    unify_kernel <<<dim3(E / 64, MTOT / 128),          256, SMEM_UNIFY>>>(bu, out);
}

// round 17
// speedup vs baseline: 1.0635x; 1.0465x over previous
#include <cuda_runtime.h>
#include <cuda_fp16.h>
#include <cstdint>

// Problem shape (fixed)
#define Bb    4
#define T     1024
#define E     512
#define H     8
#define MTOT  (Bb*T)       // 4096
#define NPROJ (H*E)        // 4096
#define BH    (Bb*H)       // 32

#define NEG_INF (__int_as_float(0xff800000))
#define QK_SCALE 0.21022410381342864f   // 512^-0.25

typedef __half f16;

// ---------------- scratch (device globals; no allocs allowed) ----------------
__device__ __align__(16) f16 g_x[MTOT * E];
__device__ __align__(16) f16 g_wk[NPROJ * E];
__device__ __align__(16) f16 g_wq[NPROJ * E];
__device__ __align__(16) f16 g_wv[NPROJ * E];
__device__ __align__(16) f16 g_wu[E * NPROJ];
__device__ __align__(16) f16 g_q[MTOT * NPROJ];        // pre-scaled
__device__ __align__(16) f16 g_k[MTOT * NPROJ];        // pre-scaled
__device__ __align__(16) f16 g_vt[(size_t)BH * E * T]; // (b,h,e,t)
__device__ __align__(16) f16 g_s[(size_t)BH * T * T];  // fp16 scores
__device__ __align__(16) f16 g_p[(size_t)BH * T * T];
__device__ __align__(16) f16 g_ao[MTOT * NPROJ];

// ---------------------------------------------------------------------------
__device__ __forceinline__ uint32_t smem_u32(const void* p) {
    uint32_t a;
    asm("{ .reg .u64 t; cvta.to.shared.u64 t, %1; cvt.u32.u64 %0, t; }" : "=r"(a) : "l"(p));
    return a;
}
__device__ __forceinline__ void cp16(uint32_t dst, const void* src) {
    asm volatile("cp.async.cg.shared.global [%0], [%1], 16;" :: "r"(dst), "l"(src) : "memory");
}
#define CP_COMMIT()  asm volatile("cp.async.commit_group;" ::: "memory")
#define CP_WAIT(n)   asm volatile("cp.async.wait_group %0;" :: "n"(n) : "memory")

__device__ __forceinline__ void ldsm4(uint32_t* r, uint32_t addr) {
    asm volatile("ldmatrix.sync.aligned.m8n8.x4.shared.b16 {%0,%1,%2,%3}, [%4];"
                 : "=r"(r[0]), "=r"(r[1]), "=r"(r[2]), "=r"(r[3]) : "r"(addr));
}
__device__ __forceinline__ void mma16816(float* c, const uint32_t* a, const uint32_t* b) {
    asm volatile(
        "mma.sync.aligned.m16n8k16.row.col.f32.f16.f16.f32 "
        "{%0,%1,%2,%3}, {%4,%5,%6,%7}, {%8,%9}, {%0,%1,%2,%3};"
        : "+f"(c[0]), "+f"(c[1]), "+f"(c[2]), "+f"(c[3])
        : "r"(a[0]), "r"(a[1]), "r"(a[2]), "r"(a[3]), "r"(b[0]), "r"(b[1]));
}

// all 5 inputs -> single fp16; each is 2M elements, float4-vectorized
__global__ void split_all(const float* __restrict__ x,  const float* __restrict__ wk,
                          const float* __restrict__ wq, const float* __restrict__ wv,
                          const float* __restrict__ wu) {
    const int i4 = blockIdx.x * 256 + threadIdx.x;    // float4 index
    const float* s; f16* d;
    switch (blockIdx.y) {
        case 0:  s = x;  d = g_x;  break;
        case 1:  s = wk; d = g_wk; break;
        case 2:  s = wq; d = g_wq; break;
        case 3:  s = wv; d = g_wv; break;
        default: s = wu; d = g_wu; break;
    }
    float4 v = ((const float4*)s)[i4];
    f16 o[4] = { __float2half(v.x), __float2half(v.y),
                 __float2half(v.z), __float2half(v.w) };
    *(uint2*)(d + i4 * 4) = *(const uint2*)o;
}

// swizzle for ROWB-byte rows; kg = 16B group.  XOR with (row & 7) keeps
// ldmatrix (8 rows, same kg) conflict-free.
template<int ROWB>
__device__ __forceinline__ uint32_t swz(int row, int kg) {
    return row * ROWB + ((kg ^ (row & 7)) << 4);
}

// ---------------------------------------------------------------------------
// GEMM core (1-mma): C[BM,BN] = A[BM,K] x B[BN,K]^T, both single fp16.
// 256 threads, warp grid 4(m) x 2(n), warp tile BM/4 x BN/2, K-chunk CK,
// 2-stage cp.async, ONE __syncthreads per chunk.
// ---------------------------------------------------------------------------
template<int BM, int BN, int CK>
__device__ __forceinline__ void tc_gemm1(
    const f16* __restrict__ A, int lda,
    const f16* __restrict__ B, int ldb,
    int K, float* acc)
{
    constexpr int WM = BM / 4, WN = BN / 2;
    constexpr int ROWB = CK * 2;
    constexpr int KG = CK / 8;            // 16B groups per row
    constexpr int SA = BM * ROWB;
    constexpr int SB = BN * ROWB;
    constexpr int STG = SA + SB;
    extern __shared__ char sm[];

    const int tid  = threadIdx.x;
    const int lane = tid & 31;
    const int warp = tid >> 5;
    const int wm = warp >> 1, wn = warp & 1;

    const int arow = ((lane >> 3) & 1) * 8 + (lane & 7);
    const int akg  = (lane >> 4) & 1;
    const int brow = ((lane >> 4) & 1) * 8 + (lane & 7);
    const int bkg  = (lane >> 3) & 1;

    #pragma unroll
    for (int i = 0; i < WM * WN / 32; i++) acc[i] = 0.f;

    const int nch = K / CK;

    auto load_chunk = [&](int i) {
        const int k0 = i * CK;
        const uint32_t st = smem_u32(sm + (i & 1) * STG);
        #pragma unroll
        for (int j = 0; j < BM * CK / 2048; j++) {     // 4 KB per 256-thread pass
            int idx = tid + j * 256;
            int r = idx / KG, kg = idx % KG;
            cp16(st + swz<ROWB>(r, kg), A + (size_t)r * lda + k0 + kg * 8);
        }
        #pragma unroll
        for (int j = 0; j < BN * CK / 2048; j++) {
            int idx = tid + j * 256;
            int r = idx / KG, kg = idx % KG;
            cp16(st + SA + swz<ROWB>(r, kg), B + (size_t)r * ldb + k0 + kg * 8);
        }
        CP_COMMIT();
    };

    load_chunk(0);

    for (int i = 0; i < nch; i++) {
        CP_WAIT(0);
        __syncthreads();
        if (i + 1 < nch) load_chunk(i + 1);

        const uint32_t st = smem_u32(sm + (i & 1) * STG);
        #pragma unroll
        for (int ks = 0; ks < CK / 16; ks++) {
            uint32_t a[WM / 16][4], b[WN / 16][4];
            #pragma unroll
            for (int im = 0; im < WM / 16; im++) {
                int row = wm * WM + im * 16 + arow;
                ldsm4(a[im], st + swz<ROWB>(row, ks * 2 + akg));
            }
            #pragma unroll
            for (int j2 = 0; j2 < WN / 16; j2++) {
                int n = wn * WN + j2 * 16 + brow;
                ldsm4(b[j2], st + SA + swz<ROWB>(n, ks * 2 + bkg));
            }
            #pragma unroll
            for (int im = 0; im < WM / 16; im++)
                #pragma unroll
                for (int jn = 0; jn < WN / 8; jn++)
                    mma16816(acc + (im * (WN / 8) + jn) * 4,
                             a[im], &b[jn >> 1][(jn & 1) * 2]);
        }
    }
}

// epilogue iteration: f(row, col, val) over this thread's fragment elements
template<int BM, int BN, typename F>
__device__ __forceinline__ void epi(const float* acc, F&& f) {
    constexpr int WM = BM / 4, WN = BN / 2;
    const int lane = threadIdx.x & 31;
    const int warp = threadIdx.x >> 5;
    const int wm = warp >> 1, wn = warp & 1;
    const int g = lane >> 2, tg = lane & 3;
    #pragma unroll
    for (int im = 0; im < WM / 16; im++)
        #pragma unroll
        for (int jn = 0; jn < WN / 8; jn++)
            #pragma unroll
            for (int r = 0; r < 4; r++) {
                int row = wm * WM + im * 16 + g + ((r & 2) ? 8 : 0);
                int col = wn * WN + jn * 8 + tg * 2 + (r & 1);
                f(row, col, acc[(im * (WN / 8) + jn) * 4 + r]);
            }
}

// BN=128/CK=64 kernels: stage (128+128)*128 = 32 KB, x2 = 64 KB
#define SMEM_G128  (2 * (128 + 128) * 128)
// proj additionally stages a 128x129 fp32 tile for the Vt transpose
#define SMEM_PROJ  (128 * 129 * 4 > SMEM_G128 ? 128 * 129 * 4 : SMEM_G128)
// unify: BN=64/CK=128, stage (128+64)*256 = 48 KB, x2 = 96 KB
#define SMEM_UNIFY (2 * (128 + 64) * 256)

// ---------------------------------------------------------------------------
// QKV projection (BM=128, BN=128, CK=64).
// z: 0 = k (scaled), 1 = q (scaled), 2 = v -> Vt (staged via smem, coalesced)
// ---------------------------------------------------------------------------
__global__ __launch_bounds__(256, 2) void proj_kernel() {
    const int n0 = blockIdx.x * 128;
    const int m0 = blockIdx.y * 128;
    const int z  = blockIdx.z;
    const f16* W = (z == 0) ? g_wk : (z == 1) ? g_wq : g_wv;

    float acc[64];
    tc_gemm1<128, 128, 64>(g_x + (size_t)m0 * E, E, W + (size_t)n0 * E, E, E, acc);

    if (z == 2) {
        extern __shared__ char sm[];
        float* smf = (float*)sm;              // 128 x 129 fp32 = 66 KB
        __syncthreads();
        epi<128, 128>(acc, [&](int row, int col, float v) {
            smf[row * 129 + col] = v;
        });
        __syncthreads();
        const int b = m0 >> 10, t_base = m0 & 1023;
        const int h = n0 >> 9,  ec_base = n0 & 511;
        const size_t vb = ((size_t)((b * H + h) * E + ec_base)) * T + t_base;
        const int tid = threadIdx.x;
        #pragma unroll
        for (int j = 0; j < 64; j++) {
            int idx = tid + j * 256;          // 16384 elements
            int ec_i = idx >> 7, t_i = idx & 127;
            g_vt[vb + (size_t)ec_i * T + t_i] = __float2half(smf[t_i * 129 + ec_i]);
        }
    } else {
        f16* D = (z == 0) ? g_k : g_q;
        epi<128, 128>(acc, [&](int row, int col, float v) {
            D[(size_t)(m0 + row) * NPROJ + n0 + col] = __float2half(v * QK_SCALE);
        });
    }
}

// ---------------------------------------------------------------------------
// Scores (BM=128 q, BN=128 k, CK=64): exact triangular grid — 36 active tiles
// per bh, decoded LJF (largest q first).  S stored fp16.
// ---------------------------------------------------------------------------
__global__ __launch_bounds__(256, 2) void scores_kernel() {
    // decode blockIdx.x in [0, 36) -> (qt descending from 7, kt in [0, qt])
    int l = blockIdx.x;
    int qt = 7, cnt = 8;
    while (l >= cnt) { l -= cnt; qt--; cnt = qt + 1; }
    const int q0 = qt * 128;
    const int k0 = l * 128;
    const int bh = blockIdx.z;
    const int b = bh >> 3, h = bh & 7;
    const size_t base = (size_t)b * T * NPROJ + (size_t)h * E;

    float acc[64];
    tc_gemm1<128, 128, 64>(g_q + base + (size_t)q0 * NPROJ, NPROJ,
                           g_k + base + (size_t)k0 * NPROJ, NPROJ, E, acc);

    f16* S = g_s + (size_t)bh * T * T;
    epi<128, 128>(acc, [&](int row, int col, float v) {
        S[(size_t)(q0 + row) * T + k0 + col] = __float2half(v);
    });
}

// ---------------------------------------------------------------------------
// Softmax, warp-per-row: 8 warps/block = 8 rows, pure shuffle reductions,
// NO __syncthreads.  Each lane handles 4 contiguous halves per j-step
// (8 steps cover T=1024); steps at or beyond kend are skipped entirely.
// ---------------------------------------------------------------------------
__global__ __launch_bounds__(256) void softmax_kernel() {
    const int warp = threadIdx.x >> 5;
    const int lane = threadIdx.x & 31;
    const int row  = blockIdx.x * 8 + warp;
    const int trow = row & 1023;
    const int kend = (trow & ~127) + 128;       // valid 128-tiles
    const int jend = kend >> 7;                 // 128 elems per j-step
    const f16* __restrict__ S = g_s + (size_t)row * T;
    f16* __restrict__ P = g_p + (size_t)row * T;

    float v[8][4];
    float m = NEG_INF;
    for (int j = 0; j < jend; j++) {
        const int base = j * 128 + lane * 4;
        f16 s4[4];
        *(uint2*)s4 = *(const uint2*)(S + base);
        #pragma unroll
        for (int i = 0; i < 4; i++) {
            v[j][i] = (base + i <= trow) ? __half2float(s4[i]) : NEG_INF;
            m = fmaxf(m, v[j][i]);
        }
    }
    #pragma unroll
    for (int o = 16; o > 0; o >>= 1) m = fmaxf(m, __shfl_xor_sync(~0u, m, o));

    float sum = 0.f;
    for (int j = 0; j < jend; j++)
        #pragma unroll
        for (int i = 0; i < 4; i++) { v[j][i] = __expf(v[j][i] - m); sum += v[j][i]; }
    #pragma unroll
    for (int o = 16; o > 0; o >>= 1) sum += __shfl_xor_sync(~0u, sum, o);

    const float inv = 1.0f / sum;
    for (int j = 0; j < jend; j++) {
        const int base = j * 128 + lane * 4;
        f16 p[4];
        #pragma unroll
        for (int i = 0; i < 4; i++) p[i] = __float2half(v[j][i] * inv);
        *(uint2*)(P + base) = *(const uint2*)p;
    }
}

// ---------------------------------------------------------------------------
// AV (BM=128 q, BN=128 e, CK=64): K truncated causally; q reversed (LJF).
// ---------------------------------------------------------------------------
__global__ __launch_bounds__(256, 2) void av_kernel() {
    const int n0 = blockIdx.x * 128;
    const int q0 = (int)(gridDim.y - 1 - blockIdx.y) * 128;
    const int bh = blockIdx.z;
    const int b = bh >> 3, h = bh & 7;
    const size_t pbase = (size_t)bh * T * T + (size_t)q0 * T;
    const size_t vbase = (size_t)bh * E * T + (size_t)n0 * T;

    float acc[64];
    tc_gemm1<128, 128, 64>(g_p + pbase, T, g_vt + vbase, T, q0 + 128, acc);

    epi<128, 128>(acc, [&](int row, int col, float v) {
        size_t o = (size_t)(b * T + q0 + row) * NPROJ + h * E + n0 + col;
        g_ao[o] = __float2half(v);
    });
}

// ---------------------------------------------------------------------------
// Unify (BM=128, BN=64, CK=128): grid 8x32 keeps the chip filled.
// out = AO @ wu^T + bu
// ---------------------------------------------------------------------------
__global__ __launch_bounds__(256, 2) void unify_kernel(const float* __restrict__ bu,
                                                       float* __restrict__ out) {
    const int n0 = blockIdx.x * 64;
    const int m0 = blockIdx.y * 128;

    float acc[32];
    tc_gemm1<128, 64, 128>(g_ao + (size_t)m0 * NPROJ, NPROJ,
                           g_wu + (size_t)n0 * NPROJ, NPROJ, NPROJ, acc);

    epi<128, 64>(acc, [&](int row, int col, float v) {
        out[(size_t)(m0 + row) * E + n0 + col] = v + bu[n0 + col];
    });
}

// ---------------------------------------------------------------------------
extern "C" void kernel_launch(void* const* d_in, const int* in_sizes, int n_in,
                              void* d_out, int out_size) {
    const float* x  = (const float*)d_in[0];
    const float* wk = (const float*)d_in[1];
    const float* wq = (const float*)d_in[2];
    const float* wv = (const float*)d_in[3];
    const float* wu = (const float*)d_in[4];
    const float* bu = (const float*)d_in[5];
    float* out = (float*)d_out;

    cudaFuncSetAttribute(proj_kernel,   cudaFuncAttributeMaxDynamicSharedMemorySize, SMEM_PROJ);
    cudaFuncSetAttribute(scores_kernel, cudaFuncAttributeMaxDynamicSharedMemorySize, SMEM_G128);
    cudaFuncSetAttribute(av_kernel,     cudaFuncAttributeMaxDynamicSharedMemorySize, SMEM_G128);
    cudaFuncSetAttribute(unify_kernel,  cudaFuncAttributeMaxDynamicSharedMemorySize, SMEM_UNIFY);

    split_all<<<dim3(MTOT * E / 1024, 5), 256>>>(x, wk, wq, wv, wu);

    proj_kernel  <<<dim3(NPROJ / 128, MTOT / 128, 3), 256, SMEM_PROJ>>>();
    scores_kernel<<<dim3(36, 1, BH),                   256, SMEM_G128>>>();
    softmax_kernel<<<BH * T / 8, 256>>>();
    av_kernel    <<<dim3(E / 128, T / 128, BH),        256, SMEM_G128>>>();
    unify_kernel <<<dim3(E / 64, MTOT / 128),          256, SMEM_UNIFY>>>(bu, out);
}